// round 1
// baseline (speedup 1.0000x reference)
#include <cuda_runtime.h>
#include <math.h>

// ---------------- problem constants ----------------
#define BB   4
#define NQ   900
#define DD   256
#define HH   8
#define HDD  32
#define LL   4
#define PP   4
#define SS   21760          // 128^2+64^2+32^2+16^2
#define DFF  1024
#define BNQ  (BB*NQ)        // 3600

// ---------------- device scratch (no allocations allowed) ----------------
__device__ float g_qp [BNQ*DD];
__device__ float g_q  [BNQ*DD];
__device__ float g_k  [BNQ*DD];
__device__ float g_v  [BNQ*DD];
__device__ float g_sa [BNQ*DD];
__device__ float g_tmp[BNQ*DD];
__device__ float g_t1 [BNQ*DD];
__device__ float g_t2 [BNQ*DD];
__device__ float g_off[BNQ*DD];
__device__ float g_acc[BNQ*DD];
__device__ float g_aw [BNQ*128];
__device__ float g_val[(long)BB*SS*DD];
__device__ float g_ffh[BNQ*DFF];

// ---------------- elementwise add ----------------
__global__ void add_k(const float* __restrict__ a, const float* __restrict__ b,
                      float* __restrict__ o, int n) {
    int i = blockIdx.x * 256 + threadIdx.x;
    if (i < n) o[i] = a[i] + b[i];
}

// ---------------- tiled SGEMM: C = A(MxK) @ W(KxN) + bias ----------------
// 64x64 tile, 256 threads, 4x4 microtile per thread.
template<int RELU, int MASK>
__global__ void gemm_k(const float* __restrict__ A, int lda,
                       const float* __restrict__ W, int ldw,
                       const float* __restrict__ bias,
                       float* __restrict__ C, int ldc,
                       int M, int N, int K,
                       const unsigned char* __restrict__ mask) {
    __shared__ float As[16][64];
    __shared__ float Ws[16][64];
    const int t  = threadIdx.x;
    const int tx = t & 15, ty = t >> 4;
    const int m0 = blockIdx.y * 64, n0 = blockIdx.x * 64;

    float acc[4][4];
    #pragma unroll
    for (int i = 0; i < 4; i++)
        #pragma unroll
        for (int j = 0; j < 4; j++) acc[i][j] = 0.f;

    for (int k0 = 0; k0 < K; k0 += 16) {
        #pragma unroll
        for (int i = 0; i < 4; i++) {
            int e = t + i * 256;
            int r = e >> 4, c = e & 15;           // A tile: 64 rows x 16 k
            int gm = m0 + r;
            As[c][r] = (gm < M) ? A[(long)gm * lda + k0 + c] : 0.f;
            int kr = e >> 6, nc = e & 63;         // W tile: 16 k x 64 n
            Ws[kr][nc] = W[(long)(k0 + kr) * ldw + n0 + nc];
        }
        __syncthreads();
        #pragma unroll
        for (int kk = 0; kk < 16; kk++) {
            float4 a4 = ((float4*)As[kk])[ty];
            float4 b4 = ((float4*)Ws[kk])[tx];
            float av[4] = {a4.x, a4.y, a4.z, a4.w};
            float bv[4] = {b4.x, b4.y, b4.z, b4.w};
            #pragma unroll
            for (int i = 0; i < 4; i++)
                #pragma unroll
                for (int j = 0; j < 4; j++)
                    acc[i][j] = fmaf(av[i], bv[j], acc[i][j]);
        }
        __syncthreads();
    }

    #pragma unroll
    for (int i = 0; i < 4; i++) {
        int gm = m0 + ty * 4 + i;
        if (gm >= M) continue;
        bool mz = MASK ? (mask[gm] != 0) : false;
        #pragma unroll
        for (int j = 0; j < 4; j++) {
            int gn = n0 + tx * 4 + j;
            float v = acc[i][j] + bias[gn];
            if (RELU) v = fmaxf(v, 0.f);
            if (mz) v = 0.f;
            C[(long)gm * ldc + gn] = v;
        }
    }
}

// ---------------- flash attention: warp per query, lane = head dim ----------------
__global__ void attn_k(const float* __restrict__ q, const float* __restrict__ k,
                       const float* __restrict__ v, float* __restrict__ sa) {
    const int bh = blockIdx.y;
    const int b = bh >> 3, h = bh & 7;
    const int warp = threadIdx.x >> 5, lane = threadIdx.x & 31;
    const int qi = blockIdx.x * 8 + warp;
    const bool valid = qi < NQ;

    __shared__ float Kc[64 * 32];
    __shared__ float Vc[64 * 32];

    float qv = 0.f;
    if (valid) qv = q[((long)(b * NQ + qi)) * DD + h * HDD + lane];

    float m = -1e30f, l = 0.f, acc = 0.f;
    const float sc = 0.17677669529663687f; // 1/sqrt(32)

    for (int kc = 0; kc < NQ; kc += 64) {
        int jmax = min(64, NQ - kc);
        for (int e = threadIdx.x; e < 64 * 32; e += 256) {
            int j = e >> 5, d = e & 31;
            int jg = kc + j;
            float kv = 0.f, vv = 0.f;
            if (jg < NQ) {
                long base = ((long)(b * NQ + jg)) * DD + h * HDD + d;
                kv = k[base]; vv = v[base];
            }
            Kc[e] = kv; Vc[e] = vv;
        }
        __syncthreads();
        if (valid) {
            for (int j = 0; j < jmax; j++) {
                float s = qv * Kc[j * 32 + lane];
                #pragma unroll
                for (int o = 16; o; o >>= 1) s += __shfl_xor_sync(0xffffffffu, s, o);
                s *= sc;
                float nm  = fmaxf(m, s);
                float cor = __expf(m - nm);
                float p   = __expf(s - nm);
                l   = l * cor + p;
                acc = acc * cor + p * Vc[j * 32 + lane];
                m = nm;
            }
        }
        __syncthreads();
    }
    if (valid) sa[((long)(b * NQ + qi)) * DD + h * HDD + lane] = acc / l;
}

// ---------------- fused residual + LayerNorm: out = LN(resid + add) ----------------
__global__ void ln_k(const float* __restrict__ resid, const float* __restrict__ add,
                     const float* __restrict__ g, const float* __restrict__ bta,
                     float* __restrict__ out) {
    const int r = blockIdx.x, tdx = threadIdx.x;
    const int wid = tdx >> 5, lane = tdx & 31;
    __shared__ float red[8];
    __shared__ float s_mean, s_rstd;

    float x = resid[(long)r * DD + tdx] + add[(long)r * DD + tdx];

    float s = x;
    #pragma unroll
    for (int o = 16; o; o >>= 1) s += __shfl_xor_sync(0xffffffffu, s, o);
    if (lane == 0) red[wid] = s;
    __syncthreads();
    if (tdx == 0) {
        float tot = 0.f;
        #pragma unroll
        for (int i = 0; i < 8; i++) tot += red[i];
        s_mean = tot * (1.f / DD);
    }
    __syncthreads();
    float mean = s_mean;
    float dx = x - mean;

    float s2 = dx * dx;
    #pragma unroll
    for (int o = 16; o; o >>= 1) s2 += __shfl_xor_sync(0xffffffffu, s2, o);
    if (lane == 0) red[wid] = s2;
    __syncthreads();
    if (tdx == 0) {
        float tot = 0.f;
        #pragma unroll
        for (int i = 0; i < 8; i++) tot += red[i];
        s_rstd = rsqrtf(tot * (1.f / DD) + 1e-5f);
    }
    __syncthreads();
    out[(long)r * DD + tdx] = dx * s_rstd * g[tdx] + bta[tdx];
}

// ---------------- attention-weight softmax over L*P=16 per (b,q,h) ----------------
__global__ void awsm_k(float* __restrict__ aw) {
    int idx = blockIdx.x * 256 + threadIdx.x;
    if (idx >= BNQ * HH) return;
    int bq = idx >> 3, h = idx & 7;
    float* p = aw + (long)bq * 128 + h * 16;
    float m = -1e30f;
    float e[16];
    #pragma unroll
    for (int i = 0; i < 16; i++) m = fmaxf(m, p[i]);
    float sum = 0.f;
    #pragma unroll
    for (int i = 0; i < 16; i++) { e[i] = __expf(p[i] - m); sum += e[i]; }
    float inv = 1.f / sum;
    #pragma unroll
    for (int i = 0; i < 16; i++) p[i] = e[i] * inv;
}

// ---------------- deformable bilinear sampling: warp per (b,q,h), lane = d ----------------
__global__ void samp_k(const float* __restrict__ off, const float* __restrict__ aw,
                       const float* __restrict__ refp, const float* __restrict__ val,
                       float* __restrict__ acc) {
    const int widx = blockIdx.x * 8 + (threadIdx.x >> 5);
    const int lane = threadIdx.x & 31;
    if (widx >= BNQ * HH) return;
    const int b = widx / (NQ * HH);
    const int rem = widx % (NQ * HH);
    const int qI = rem / HH, h = rem % HH;

    const int dims[4]   = {128, 64, 32, 16};
    const int starts[4] = {0, 16384, 20480, 21504};

    const long obase = ((long)(b * NQ + qI)) * DD + h * HDD;   // off row base
    const long abase = ((long)(b * NQ + qI)) * 128 + h * 16;   // aw row base
    const long vbase = (long)b * SS;                           // value row base

    float a = 0.f;
    #pragma unroll
    for (int l = 0; l < 4; l++) {
        const int Wl = dims[l], Hl = dims[l], st = starts[l];
        float rx = refp[(((long)(b * NQ + qI)) * LL + l) * 2 + 0];
        float ry = refp[(((long)(b * NQ + qI)) * LL + l) * 2 + 1];
        #pragma unroll
        for (int p = 0; p < 4; p++) {
            float x = rx * Wl + off[obase + l * 8 + p * 2 + 0] - 0.5f;
            float y = ry * Hl + off[obase + l * 8 + p * 2 + 1] - 0.5f;
            float x0f = floorf(x), y0f = floorf(y);
            int x0 = (int)x0f, y0 = (int)y0f;
            float wx = x - x0f, wy = y - y0f;
            float w = aw[abase + l * 4 + p];

            float cw[4] = {(1.f - wx) * (1.f - wy), wx * (1.f - wy),
                           (1.f - wx) * wy,          wx * wy};
            int xs[4] = {x0, x0 + 1, x0,     x0 + 1};
            int ys[4] = {y0, y0,     y0 + 1, y0 + 1};
            #pragma unroll
            for (int c = 0; c < 4; c++) {
                int xi = xs[c], yi = ys[c];
                if (xi >= 0 && xi < Wl && yi >= 0 && yi < Hl) {
                    a += w * cw[c] *
                         val[((vbase + st + (long)yi * Wl + xi)) * DD + h * HDD + lane];
                }
            }
        }
    }
    acc[obase + lane] = a;
}

// ---------------- host launch ----------------
static inline void launch_gemm(const float* A, int lda, const float* W, int ldw,
                               const float* bias, float* C, int M, int N, int K,
                               int relu, const unsigned char* mask) {
    dim3 grid(N / 64, (M + 63) / 64);
    if (mask)      gemm_k<0, 1><<<grid, 256>>>(A, lda, W, ldw, bias, C, N, M, N, K, mask);
    else if (relu) gemm_k<1, 0><<<grid, 256>>>(A, lda, W, ldw, bias, C, N, M, N, K, nullptr);
    else           gemm_k<0, 0><<<grid, 256>>>(A, lda, W, ldw, bias, C, N, M, N, K, nullptr);
}

extern "C" void kernel_launch(void* const* d_in, const int* in_sizes, int n_in,
                              void* d_out, int out_size) {
    const float* tgt        = (const float*)d_in[0];
    const float* query_pos  = (const float*)d_in[1];
    const float* refp       = (const float*)d_in[2];
    const float* memory     = (const float*)d_in[3];
    const float* in_proj_w  = (const float*)d_in[4];
    const float* in_proj_b  = (const float*)d_in[5];
    const float* out_proj_w = (const float*)d_in[6];
    const float* out_proj_b = (const float*)d_in[7];
    const float* ln1_g      = (const float*)d_in[8];
    const float* ln1_b      = (const float*)d_in[9];
    const float* ln2_g      = (const float*)d_in[10];
    const float* ln2_b      = (const float*)d_in[11];
    const float* ln3_g      = (const float*)d_in[12];
    const float* ln3_b      = (const float*)d_in[13];
    const float* vproj_w    = (const float*)d_in[14];
    const float* vproj_b    = (const float*)d_in[15];
    const float* off_w      = (const float*)d_in[16];
    const float* off_b      = (const float*)d_in[17];
    const float* aw_w       = (const float*)d_in[18];
    const float* aw_b       = (const float*)d_in[19];
    const float* oproj_w    = (const float*)d_in[20];
    const float* oproj_b    = (const float*)d_in[21];
    const float* lin1_w     = (const float*)d_in[22];
    const float* lin1_b     = (const float*)d_in[23];
    const float* lin2_w     = (const float*)d_in[24];
    const float* lin2_b     = (const float*)d_in[25];
    // d_in[26] = spatial_shapes (constant, hardcoded), d_in[27] = mem_mask
    const unsigned char* mem_mask = (const unsigned char*)d_in[27];
    float* out = (float*)d_out;

    float *qp, *q, *k, *v, *sa, *tmp, *t1, *t2, *offb, *accb, *awb, *valb, *ffh;
    cudaGetSymbolAddress((void**)&qp,  g_qp);
    cudaGetSymbolAddress((void**)&q,   g_q);
    cudaGetSymbolAddress((void**)&k,   g_k);
    cudaGetSymbolAddress((void**)&v,   g_v);
    cudaGetSymbolAddress((void**)&sa,  g_sa);
    cudaGetSymbolAddress((void**)&tmp, g_tmp);
    cudaGetSymbolAddress((void**)&t1,  g_t1);
    cudaGetSymbolAddress((void**)&t2,  g_t2);
    cudaGetSymbolAddress((void**)&offb, g_off);
    cudaGetSymbolAddress((void**)&accb, g_acc);
    cudaGetSymbolAddress((void**)&awb,  g_aw);
    cudaGetSymbolAddress((void**)&valb, g_val);
    cudaGetSymbolAddress((void**)&ffh,  g_ffh);

    const int NE = BNQ * DD;

    // 1) qp = tgt + query_pos
    add_k<<<(NE + 255) / 256, 256>>>(tgt, query_pos, qp, NE);

    // 2) q/k/v projections (in_proj_w is D x 3D row-major)
    launch_gemm(qp,  DD, in_proj_w,           3 * DD, in_proj_b,          q, BNQ, DD, DD, 0, nullptr);
    launch_gemm(qp,  DD, in_proj_w + DD,      3 * DD, in_proj_b + DD,     k, BNQ, DD, DD, 0, nullptr);
    launch_gemm(tgt, DD, in_proj_w + 2 * DD,  3 * DD, in_proj_b + 2 * DD, v, BNQ, DD, DD, 0, nullptr);

    // 3) self-attention
    attn_k<<<dim3((NQ + 7) / 8, BB * HH), 256>>>(q, k, v, sa);

    // 4) out_proj + residual LN2 -> t1
    launch_gemm(sa, DD, out_proj_w, DD, out_proj_b, tmp, BNQ, DD, DD, 0, nullptr);
    ln_k<<<BNQ, DD>>>(tgt, tmp, ln2_g, ln2_b, t1);

    // 5) query = t1 + query_pos  (reuse qp)
    add_k<<<(NE + 255) / 256, 256>>>(t1, query_pos, qp, NE);

    // 6) value projection with mask
    launch_gemm(memory, DD, vproj_w, DD, vproj_b, valb, BB * SS, DD, DD, 0, mem_mask);

    // 7) sampling offsets + attention weights
    launch_gemm(qp, DD, off_w, DD, off_b, offb, BNQ, DD,  DD, 0, nullptr);
    launch_gemm(qp, DD, aw_w, 128, aw_b,  awb,  BNQ, 128, DD, 0, nullptr);
    awsm_k<<<(BNQ * HH + 255) / 256, 256>>>(awb);

    // 8) deformable sampling
    samp_k<<<(BNQ * HH) / 8, 256>>>(offb, awb, refp, valb, accb);

    // 9) output projection + residual LN1 -> t2
    launch_gemm(accb, DD, oproj_w, DD, oproj_b, tmp, BNQ, DD, DD, 0, nullptr);
    ln_k<<<BNQ, DD>>>(t1, tmp, ln1_g, ln1_b, t2);

    // 10) FFN + residual LN3 -> out
    launch_gemm(t2, DD, lin1_w, DFF, lin1_b, ffh, BNQ, DFF, DD, 1, nullptr);
    launch_gemm(ffh, DFF, lin2_w, DD, lin2_b, tmp, BNQ, DD, DFF, 0, nullptr);
    ln_k<<<BNQ, DD>>>(t2, tmp, ln3_g, ln3_b, out);
}

// round 2
// speedup vs baseline: 1.8688x; 1.8688x over previous
#include <cuda_runtime.h>
#include <math.h>
#include <stdint.h>

// ---------------- problem constants ----------------
#define BB   4
#define NQ   900
#define DD   256
#define HH   8
#define HDD  32
#define LL   4
#define PP   4
#define SS   21760          // 128^2+64^2+32^2+16^2
#define DFF  1024
#define BNQ  (BB*NQ)        // 3600

// ---------------- device scratch (no allocations allowed) ----------------
__device__ float g_qp [BNQ*DD];
__device__ float g_q  [BNQ*DD];
__device__ float g_k  [BNQ*DD];
__device__ float g_v  [BNQ*DD];
__device__ float g_sa [BNQ*DD];
__device__ float g_tmp[BNQ*DD];
__device__ float g_t1 [BNQ*DD];
__device__ float g_t2 [BNQ*DD];
__device__ float g_off[BNQ*DD];
__device__ float g_acc[BNQ*DD];
__device__ float g_aw [BNQ*128];
__device__ float g_val[(long)BB*SS*DD];
__device__ float g_ffh[BNQ*DFF];

// ---------------- elementwise add ----------------
__global__ void add_k(const float* __restrict__ a, const float* __restrict__ b,
                      float* __restrict__ o, int n) {
    int i = blockIdx.x * 256 + threadIdx.x;
    if (i < n) o[i] = a[i] + b[i];
}

// ---------------- tf32 helpers ----------------
__device__ __forceinline__ float to_tf32(float x) {
    uint32_t o;
    asm("cvt.rna.tf32.f32 %0, %1;" : "=r"(o) : "f"(x));
    return __uint_as_float(o);
}

__device__ __forceinline__ void mma_tf32(float c[4],
                                         uint32_t a0, uint32_t a1, uint32_t a2, uint32_t a3,
                                         uint32_t b0, uint32_t b1) {
    asm volatile(
        "mma.sync.aligned.m16n8k8.row.col.f32.tf32.tf32.f32 "
        "{%0,%1,%2,%3}, {%4,%5,%6,%7}, {%8,%9}, {%0,%1,%2,%3};\n"
        : "+f"(c[0]), "+f"(c[1]), "+f"(c[2]), "+f"(c[3])
        : "r"(a0), "r"(a1), "r"(a2), "r"(a3), "r"(b0), "r"(b1));
}

// ---------------- TF32 tensor-core GEMM: C = A(MxK) @ W(KxN) + bias ----------------
// Block tile 128x128x16, 256 threads (8 warps), warp tile 32x64.
// A stored k-major in smem As[k][m] (stride 136 -> conflict-free frag reads),
// W stored k-major Bs[k][n] (stride 136).
// Requires: K % 16 == 0, N % 128 == 0. M guarded.
#define BM 128
#define BN 128
#define BKg 16
#define LDS_P 136    // 136 % 32 == 8 -> conflict-free fragment reads

template<int RELU, int MASK>
__global__ void __launch_bounds__(256, 2)
gemm_tc(const float* __restrict__ A, int lda,
        const float* __restrict__ W, int ldw,
        const float* __restrict__ bias,
        float* __restrict__ C,
        int M, int N, int K,
        const unsigned char* __restrict__ mask) {
    __shared__ float As[BKg][LDS_P];
    __shared__ float Bs[BKg][LDS_P];

    const int t    = threadIdx.x;
    const int lane = t & 31;
    const int wid  = t >> 5;
    const int warpM = (wid >> 1) * 32;   // 0,32,64,96
    const int warpN = (wid & 1) * 64;    // 0,64
    const int m0b = blockIdx.y * BM;
    const int n0b = blockIdx.x * BN;

    float acc[2][8][4];
    #pragma unroll
    for (int i = 0; i < 2; i++)
        #pragma unroll
        for (int j = 0; j < 8; j++)
            #pragma unroll
            for (int r = 0; r < 4; r++) acc[i][j][r] = 0.f;

    // load indices
    const int arow = t >> 1;            // 0..127 : A tile row (two threads per row)
    const int akq  = (t & 1) * 8;       // k offset 0 or 8 (two float4s)
    const int brow = t >> 5;            // 0..7 : W tile k-row (first half); +8 second
    const int bcol = (t & 31) * 4;      // 0..124

    for (int k0 = 0; k0 < K; k0 += BKg) {
        // --- load A tile: 128 rows x 16 k ---
        {
            int gm = m0b + arow;
            float4 f1 = make_float4(0.f, 0.f, 0.f, 0.f), f2 = f1;
            if (gm < M) {
                const float* p = A + (long)gm * lda + k0 + akq;
                f1 = *(const float4*)p;
                f2 = *(const float4*)(p + 4);
            }
            As[akq + 0][arow] = to_tf32(f1.x);
            As[akq + 1][arow] = to_tf32(f1.y);
            As[akq + 2][arow] = to_tf32(f1.z);
            As[akq + 3][arow] = to_tf32(f1.w);
            As[akq + 4][arow] = to_tf32(f2.x);
            As[akq + 5][arow] = to_tf32(f2.y);
            As[akq + 6][arow] = to_tf32(f2.z);
            As[akq + 7][arow] = to_tf32(f2.w);
        }
        // --- load W tile: 16 k x 128 n ---
        #pragma unroll
        for (int h = 0; h < 2; h++) {
            int kr = brow + h * 8;
            float4 f = *(const float4*)(W + (long)(k0 + kr) * ldw + n0b + bcol);
            float4 g;
            g.x = to_tf32(f.x); g.y = to_tf32(f.y);
            g.z = to_tf32(f.z); g.w = to_tf32(f.w);
            *(float4*)&Bs[kr][bcol] = g;
        }
        __syncthreads();

        // --- compute: 2 k-steps of 8 ---
        #pragma unroll
        for (int ks = 0; ks < 2; ks++) {
            const int kr = ks * 8 + (lane & 3);
            const int mo = warpM + (lane >> 2);
            uint32_t af[2][4];
            #pragma unroll
            for (int i = 0; i < 2; i++) {
                af[i][0] = __float_as_uint(As[kr    ][mo + 16 * i    ]);
                af[i][1] = __float_as_uint(As[kr    ][mo + 16 * i + 8]);
                af[i][2] = __float_as_uint(As[kr + 4][mo + 16 * i    ]);
                af[i][3] = __float_as_uint(As[kr + 4][mo + 16 * i + 8]);
            }
            uint32_t bf[8][2];
            const int no = warpN + (lane >> 2);
            #pragma unroll
            for (int j = 0; j < 8; j++) {
                bf[j][0] = __float_as_uint(Bs[kr    ][no + 8 * j]);
                bf[j][1] = __float_as_uint(Bs[kr + 4][no + 8 * j]);
            }
            #pragma unroll
            for (int i = 0; i < 2; i++)
                #pragma unroll
                for (int j = 0; j < 8; j++)
                    mma_tf32(acc[i][j], af[i][0], af[i][1], af[i][2], af[i][3],
                             bf[j][0], bf[j][1]);
        }
        __syncthreads();
    }

    // --- epilogue ---
    #pragma unroll
    for (int i = 0; i < 2; i++) {
        #pragma unroll
        for (int half = 0; half < 2; half++) {
            int gm = m0b + warpM + 16 * i + (lane >> 2) + half * 8;
            if (gm >= M) continue;
            bool mz = MASK ? (mask[gm] != 0) : false;
            #pragma unroll
            for (int j = 0; j < 8; j++) {
                int gn = n0b + warpN + 8 * j + 2 * (lane & 3);
                float v0 = acc[i][j][half * 2 + 0] + bias[gn];
                float v1 = acc[i][j][half * 2 + 1] + bias[gn + 1];
                if (RELU) { v0 = fmaxf(v0, 0.f); v1 = fmaxf(v1, 0.f); }
                if (mz)   { v0 = 0.f; v1 = 0.f; }
                *(float2*)(C + (long)gm * N + gn) = make_float2(v0, v1);
            }
        }
    }
}

// ---------------- flash attention: warp per query, lane = key within tile ----------------
__global__ void attn_k(const float* __restrict__ q, const float* __restrict__ k,
                       const float* __restrict__ v, float* __restrict__ sa) {
    const int bh = blockIdx.y;
    const int b = bh >> 3, h = bh & 7;
    const int warp = threadIdx.x >> 5, lane = threadIdx.x & 31;
    const int qi = blockIdx.x * 8 + warp;
    const bool valid = qi < NQ;

    __shared__ float Kt[32][65];   // [d][j]  (pad 65 -> conflict-free both phases)
    __shared__ float Vc[64][32];   // [j][d]

    float qreg[32];
    {
        float qv = 0.f;
        if (valid) qv = q[((long)(b * NQ + qi)) * DD + h * HDD + lane];
        #pragma unroll
        for (int d = 0; d < 32; d++) qreg[d] = __shfl_sync(0xffffffffu, qv, d);
    }

    float m = -1e30f, l = 0.f, acc = 0.f;
    const float sc = 0.17677669529663687f; // 1/sqrt(32)

    for (int kc = 0; kc < NQ; kc += 64) {
        // cooperative load of 64 keys
        for (int e = threadIdx.x; e < 64 * 32; e += 256) {
            int j = e >> 5, d = e & 31;
            int jg = kc + j;
            float kv = 0.f, vv = 0.f;
            if (jg < NQ) {
                long base = ((long)(b * NQ + jg)) * DD + h * HDD + d;
                kv = k[base]; vv = v[base];
            }
            Kt[d][j]  = kv;
            Vc[j][d]  = vv;
        }
        __syncthreads();
        if (valid) {
            #pragma unroll
            for (int sub = 0; sub < 2; sub++) {
                int j0 = kc + sub * 32;
                if (j0 >= NQ) break;
                int jmax = min(32, NQ - j0);

                float s = -1e30f;
                if (lane < jmax) {
                    float t = 0.f;
                    #pragma unroll
                    for (int d = 0; d < 32; d++)
                        t = fmaf(qreg[d], Kt[d][sub * 32 + lane], t);
                    s = t * sc;
                }
                // tile max
                float tm = s;
                #pragma unroll
                for (int o = 16; o; o >>= 1)
                    tm = fmaxf(tm, __shfl_xor_sync(0xffffffffu, tm, o));
                float nm  = fmaxf(m, tm);
                float cor = __expf(m - nm);
                float p   = (lane < jmax) ? __expf(s - nm) : 0.f;

                acc *= cor;
                float psum = 0.f;
                #pragma unroll
                for (int j = 0; j < 32; j++) {
                    float pj = __shfl_sync(0xffffffffu, p, j);
                    psum += pj;
                    acc = fmaf(pj, Vc[sub * 32 + j][lane], acc);
                }
                l = l * cor + psum;
                m = nm;
            }
        }
        __syncthreads();
    }
    if (valid) sa[((long)(b * NQ + qi)) * DD + h * HDD + lane] = acc / l;
}

// ---------------- fused residual + LayerNorm: out = LN(resid + add) ----------------
__global__ void ln_k(const float* __restrict__ resid, const float* __restrict__ add,
                     const float* __restrict__ g, const float* __restrict__ bta,
                     float* __restrict__ out) {
    const int r = blockIdx.x, tdx = threadIdx.x;
    const int wid = tdx >> 5, lane = tdx & 31;
    __shared__ float red[8];
    __shared__ float s_mean, s_rstd;

    float x = resid[(long)r * DD + tdx] + add[(long)r * DD + tdx];

    float s = x;
    #pragma unroll
    for (int o = 16; o; o >>= 1) s += __shfl_xor_sync(0xffffffffu, s, o);
    if (lane == 0) red[wid] = s;
    __syncthreads();
    if (tdx == 0) {
        float tot = 0.f;
        #pragma unroll
        for (int i = 0; i < 8; i++) tot += red[i];
        s_mean = tot * (1.f / DD);
    }
    __syncthreads();
    float mean = s_mean;
    float dx = x - mean;

    float s2 = dx * dx;
    #pragma unroll
    for (int o = 16; o; o >>= 1) s2 += __shfl_xor_sync(0xffffffffu, s2, o);
    if (lane == 0) red[wid] = s2;
    __syncthreads();
    if (tdx == 0) {
        float tot = 0.f;
        #pragma unroll
        for (int i = 0; i < 8; i++) tot += red[i];
        s_rstd = rsqrtf(tot * (1.f / DD) + 1e-5f);
    }
    __syncthreads();
    out[(long)r * DD + tdx] = dx * s_rstd * g[tdx] + bta[tdx];
}

// ---------------- attention-weight softmax over L*P=16 per (b,q,h) ----------------
__global__ void awsm_k(float* __restrict__ aw) {
    int idx = blockIdx.x * 256 + threadIdx.x;
    if (idx >= BNQ * HH) return;
    int bq = idx >> 3, h = idx & 7;
    float* p = aw + (long)bq * 128 + h * 16;
    float m = -1e30f;
    float e[16];
    #pragma unroll
    for (int i = 0; i < 16; i++) m = fmaxf(m, p[i]);
    float sum = 0.f;
    #pragma unroll
    for (int i = 0; i < 16; i++) { e[i] = __expf(p[i] - m); sum += e[i]; }
    float inv = 1.f / sum;
    #pragma unroll
    for (int i = 0; i < 16; i++) p[i] = e[i] * inv;
}

// ---------------- deformable bilinear sampling: warp per (b,q,h), lane = d ----------------
__global__ void samp_k(const float* __restrict__ off, const float* __restrict__ aw,
                       const float* __restrict__ refp, const float* __restrict__ val,
                       float* __restrict__ acc) {
    const int widx = blockIdx.x * 8 + (threadIdx.x >> 5);
    const int lane = threadIdx.x & 31;
    if (widx >= BNQ * HH) return;
    const int b = widx / (NQ * HH);
    const int rem = widx % (NQ * HH);
    const int qI = rem / HH, h = rem % HH;

    const int dims[4]   = {128, 64, 32, 16};
    const int starts[4] = {0, 16384, 20480, 21504};

    const long obase = ((long)(b * NQ + qI)) * DD + h * HDD;
    const long abase = ((long)(b * NQ + qI)) * 128 + h * 16;
    const long vbase = (long)b * SS;

    float a = 0.f;
    #pragma unroll
    for (int l = 0; l < 4; l++) {
        const int Wl = dims[l], Hl = dims[l], st = starts[l];
        float rx = refp[(((long)(b * NQ + qI)) * LL + l) * 2 + 0];
        float ry = refp[(((long)(b * NQ + qI)) * LL + l) * 2 + 1];
        #pragma unroll
        for (int p = 0; p < 4; p++) {
            float x = rx * Wl + off[obase + l * 8 + p * 2 + 0] - 0.5f;
            float y = ry * Hl + off[obase + l * 8 + p * 2 + 1] - 0.5f;
            float x0f = floorf(x), y0f = floorf(y);
            int x0 = (int)x0f, y0 = (int)y0f;
            float wx = x - x0f, wy = y - y0f;
            float w = aw[abase + l * 4 + p];

            float cw[4] = {(1.f - wx) * (1.f - wy), wx * (1.f - wy),
                           (1.f - wx) * wy,          wx * wy};
            int xs[4] = {x0, x0 + 1, x0,     x0 + 1};
            int ys[4] = {y0, y0,     y0 + 1, y0 + 1};
            #pragma unroll
            for (int c = 0; c < 4; c++) {
                int xi = xs[c], yi = ys[c];
                if (xi >= 0 && xi < Wl && yi >= 0 && yi < Hl) {
                    a += w * cw[c] *
                         val[((vbase + st + (long)yi * Wl + xi)) * DD + h * HDD + lane];
                }
            }
        }
    }
    acc[obase + lane] = a;
}

// ---------------- host launch ----------------
static inline void launch_gemm(const float* A, int lda, const float* W, int ldw,
                               const float* bias, float* C, int M, int N, int K,
                               int relu, const unsigned char* mask) {
    dim3 grid(N / BN, (M + BM - 1) / BM);
    if (mask)      gemm_tc<0, 1><<<grid, 256>>>(A, lda, W, ldw, bias, C, M, N, K, mask);
    else if (relu) gemm_tc<1, 0><<<grid, 256>>>(A, lda, W, ldw, bias, C, M, N, K, nullptr);
    else           gemm_tc<0, 0><<<grid, 256>>>(A, lda, W, ldw, bias, C, M, N, K, nullptr);
}

extern "C" void kernel_launch(void* const* d_in, const int* in_sizes, int n_in,
                              void* d_out, int out_size) {
    const float* tgt        = (const float*)d_in[0];
    const float* query_pos  = (const float*)d_in[1];
    const float* refp       = (const float*)d_in[2];
    const float* memory     = (const float*)d_in[3];
    const float* in_proj_w  = (const float*)d_in[4];
    const float* in_proj_b  = (const float*)d_in[5];
    const float* out_proj_w = (const float*)d_in[6];
    const float* out_proj_b = (const float*)d_in[7];
    const float* ln1_g      = (const float*)d_in[8];
    const float* ln1_b      = (const float*)d_in[9];
    const float* ln2_g      = (const float*)d_in[10];
    const float* ln2_b      = (const float*)d_in[11];
    const float* ln3_g      = (const float*)d_in[12];
    const float* ln3_b      = (const float*)d_in[13];
    const float* vproj_w    = (const float*)d_in[14];
    const float* vproj_b    = (const float*)d_in[15];
    const float* off_w      = (const float*)d_in[16];
    const float* off_b      = (const float*)d_in[17];
    const float* aw_w       = (const float*)d_in[18];
    const float* aw_b       = (const float*)d_in[19];
    const float* oproj_w    = (const float*)d_in[20];
    const float* oproj_b    = (const float*)d_in[21];
    const float* lin1_w     = (const float*)d_in[22];
    const float* lin1_b     = (const float*)d_in[23];
    const float* lin2_w     = (const float*)d_in[24];
    const float* lin2_b     = (const float*)d_in[25];
    const unsigned char* mem_mask = (const unsigned char*)d_in[27];
    float* out = (float*)d_out;

    float *qp, *q, *k, *v, *sa, *tmp, *t1, *t2, *offb, *accb, *awb, *valb, *ffh;
    cudaGetSymbolAddress((void**)&qp,  g_qp);
    cudaGetSymbolAddress((void**)&q,   g_q);
    cudaGetSymbolAddress((void**)&k,   g_k);
    cudaGetSymbolAddress((void**)&v,   g_v);
    cudaGetSymbolAddress((void**)&sa,  g_sa);
    cudaGetSymbolAddress((void**)&tmp, g_tmp);
    cudaGetSymbolAddress((void**)&t1,  g_t1);
    cudaGetSymbolAddress((void**)&t2,  g_t2);
    cudaGetSymbolAddress((void**)&offb, g_off);
    cudaGetSymbolAddress((void**)&accb, g_acc);
    cudaGetSymbolAddress((void**)&awb,  g_aw);
    cudaGetSymbolAddress((void**)&valb, g_val);
    cudaGetSymbolAddress((void**)&ffh,  g_ffh);

    const int NE = BNQ * DD;

    // 1) qp = tgt + query_pos
    add_k<<<(NE + 255) / 256, 256>>>(tgt, query_pos, qp, NE);

    // 2) q/k/v projections (in_proj_w is D x 3D row-major)
    launch_gemm(qp,  DD, in_proj_w,           3 * DD, in_proj_b,          q, BNQ, DD, DD, 0, nullptr);
    launch_gemm(qp,  DD, in_proj_w + DD,      3 * DD, in_proj_b + DD,     k, BNQ, DD, DD, 0, nullptr);
    launch_gemm(tgt, DD, in_proj_w + 2 * DD,  3 * DD, in_proj_b + 2 * DD, v, BNQ, DD, DD, 0, nullptr);

    // 3) self-attention
    attn_k<<<dim3((NQ + 7) / 8, BB * HH), 256>>>(q, k, v, sa);

    // 4) out_proj + residual LN2 -> t1
    launch_gemm(sa, DD, out_proj_w, DD, out_proj_b, tmp, BNQ, DD, DD, 0, nullptr);
    ln_k<<<BNQ, DD>>>(tgt, tmp, ln2_g, ln2_b, t1);

    // 5) query = t1 + query_pos  (reuse qp)
    add_k<<<(NE + 255) / 256, 256>>>(t1, query_pos, qp, NE);

    // 6) value projection with mask
    launch_gemm(memory, DD, vproj_w, DD, vproj_b, valb, BB * SS, DD, DD, 0, mem_mask);

    // 7) sampling offsets + attention weights
    launch_gemm(qp, DD, off_w, DD, off_b, offb, BNQ, DD,  DD, 0, nullptr);
    launch_gemm(qp, DD, aw_w, 128, aw_b,  awb,  BNQ, 128, DD, 0, nullptr);
    awsm_k<<<(BNQ * HH + 255) / 256, 256>>>(awb);

    // 8) deformable sampling
    samp_k<<<(BNQ * HH) / 8, 256>>>(offb, awb, refp, valb, accb);

    // 9) output projection + residual LN1 -> t2
    launch_gemm(accb, DD, oproj_w, DD, oproj_b, tmp, BNQ, DD, DD, 0, nullptr);
    ln_k<<<BNQ, DD>>>(t1, tmp, ln1_g, ln1_b, t2);

    // 10) FFN + residual LN3 -> out
    launch_gemm(t2, DD, lin1_w, DFF, lin1_b, ffh, BNQ, DFF, DD, 1, nullptr);
    launch_gemm(ffh, DFF, lin2_w, DD, lin2_b, tmp, BNQ, DD, DFF, 0, nullptr);
    ln_k<<<BNQ, DD>>>(t2, tmp, ln3_g, ln3_b, out);
}